// round 7
// baseline (speedup 1.0000x reference)
#include <cuda_runtime.h>
#include <cuda_bf16.h>
#include <cstdint>

// ---------------------------------------------------------------------------
// AttentionIn: out = concat(residual, q, k, v)
//   q/k = rotary(x @ W_{Q,K} + b, first 64 dims per head); v = x @ W_V + b (NO rotary)
// Shapes: x[8192,2048], W[16,2048,128] x3, b[16,128] x3, out 4x(8192x2048) f32
// ---------------------------------------------------------------------------

#define TOKENS   8192
#define DMODEL   2048
#define DHEAD    128
#define NHEADS   16
#define SEQLEN   2048
#define ROT_DIM  64

#define BM 128
#define BN 128
#define BK 32
#define LDA 36     // A smem stride (floats): (4r+c)%32 unique -> conflict-free
#define LDB 132    // B smem stride (floats): (4c+g)%32 unique -> conflict-free
#define A_F (BM * LDA)            // 4608 floats
#define B_F (BK * LDB)            // 4224 floats
#define STAGE_F (A_F + B_F)       // 8832 floats
#define SMEM_BYTES (2 * STAGE_F * 4)  // 70656 bytes

// sin/cos table: [pos 0..2047][pair 0..31] -> (sin, cos)
__device__ float2 g_sincos[SEQLEN * 32];

// ---------------------------------------------------------------------------
__global__ void sincos_kernel() {
    int idx = blockIdx.x * blockDim.x + threadIdx.x;   // 65536 threads
    int pos = idx >> 5;
    int i   = idx & 31;
    float freq = powf(10000.0f, (float)i * (1.0f / 32.0f));
    float ang  = (float)pos / freq;
    g_sincos[idx] = make_float2(sinf(ang), cosf(ang));
}

// ---------------------------------------------------------------------------
__global__ void copy_kernel(float4* __restrict__ dst, const float4* __restrict__ src, int n) {
    int i = blockIdx.x * blockDim.x + threadIdx.x;
    int stride = gridDim.x * blockDim.x;
    for (; i < n; i += stride) dst[i] = src[i];
}

// ---------------------------------------------------------------------------
__device__ __forceinline__ void cp_async16(void* smem_ptr, const void* gmem_ptr) {
    unsigned s = (unsigned)__cvta_generic_to_shared(smem_ptr);
    asm volatile("cp.async.cg.shared.global [%0], [%1], 16;\n" :: "r"(s), "l"(gmem_ptr));
}
__device__ __forceinline__ void cp_commit() {
    asm volatile("cp.async.commit_group;\n");
}
template <int N>
__device__ __forceinline__ void cp_wait() {
    asm volatile("cp.async.wait_group %0;\n" :: "n"(N));
}

__device__ __forceinline__ uint32_t f2tf32(float f) {
    uint32_t r;
    asm("cvt.rna.tf32.f32 %0, %1;" : "=r"(r) : "f"(f));
    return r;
}

__device__ __forceinline__ void mma_tf32(float (&d)[4], const uint32_t (&a)[4],
                                         const uint32_t (&b)[2]) {
    asm volatile(
        "mma.sync.aligned.m16n8k8.row.col.f32.tf32.tf32.f32 "
        "{%0,%1,%2,%3}, {%4,%5,%6,%7}, {%8,%9}, {%0,%1,%2,%3};"
        : "+f"(d[0]), "+f"(d[1]), "+f"(d[2]), "+f"(d[3])
        : "r"(a[0]), "r"(a[1]), "r"(a[2]), "r"(a[3]), "r"(b[0]), "r"(b[1]));
}

// ---------------------------------------------------------------------------
// gridDim = (48 [mat*16+head], 64 [M tiles]), 256 threads, 8 warps (4m x 2n)
__global__ void __launch_bounds__(256, 2)
qkv_gemm_kernel(const float* __restrict__ x,
                const float* __restrict__ WQ, const float* __restrict__ WK,
                const float* __restrict__ WV,
                const float* __restrict__ bQ, const float* __restrict__ bK,
                const float* __restrict__ bV,
                float* __restrict__ out) {
    extern __shared__ float smem[];

    const int nb   = blockIdx.x;           // 0..47
    const int mb   = blockIdx.y;           // 0..63
    const int mat  = nb >> 4;              // 0=Q, 1=K, 2=V
    const int head = nb & 15;

    const float* Wsel = (mat == 0) ? WQ : (mat == 1) ? WK : WV;
    const float* bsel = (mat == 0) ? bQ : (mat == 1) ? bK : bV;
    const float* Ag = x + (size_t)mb * BM * DMODEL;
    const float* Bg = Wsel + (size_t)head * DMODEL * DHEAD;   // row-major [2048][128]
    const float* bias = bsel + head * DHEAD;
    float* Og = out + (size_t)(mat + 1) * TOKENS * DMODEL + head * DHEAD;

    // rotary applies to Q and K only — V is a plain projection
    const bool do_rot = (mat < 2);

    const int tid    = threadIdx.x;
    const int wid    = tid >> 5;
    const int lane   = tid & 31;
    const int warp_m = wid >> 1;           // 0..3 -> m offset *32
    const int warp_n = wid & 1;            // 0..1 -> n offset *64
    const int g      = lane >> 2;          // groupID
    const int c      = lane & 3;           // threadID_in_group

    float acc[2][8][4];
#pragma unroll
    for (int mi = 0; mi < 2; mi++)
#pragma unroll
        for (int ni = 0; ni < 8; ni++)
#pragma unroll
            for (int r = 0; r < 4; r++) acc[mi][ni][r] = 0.0f;

    // ---- stage loader ----
    auto load_stage = [&](int buf, int k0) {
        float* As = smem + buf * STAGE_F;
        float* Bs = As + A_F;
#pragma unroll
        for (int i = 0; i < 4; i++) {          // A: 1024 x 16B segs
            int id = tid + i * 256;
            int r = id >> 3, s = id & 7;
            cp_async16(As + r * LDA + s * 4, Ag + (size_t)r * DMODEL + k0 + s * 4);
        }
#pragma unroll
        for (int i = 0; i < 4; i++) {          // B: 1024 x 16B segs
            int id = tid + i * 256;
            int r = id >> 5, s = id & 31;
            cp_async16(Bs + r * LDB + s * 4, Bg + (size_t)(k0 + r) * DHEAD + s * 4);
        }
        cp_commit();
    };

    const int KT = DMODEL / BK;   // 64
    load_stage(0, 0);

    for (int kt = 0; kt < KT; kt++) {
        if (kt + 1 < KT) {
            load_stage((kt + 1) & 1, (kt + 1) * BK);
            cp_wait<1>();
        } else {
            cp_wait<0>();
        }
        __syncthreads();

        const float* As = smem + (kt & 1) * STAGE_F;
        const float* Bs = As + A_F;

#pragma unroll
        for (int ks = 0; ks < 4; ks++) {
            const int kk = ks * 8 + c;
            uint32_t a[2][4];
#pragma unroll
            for (int mi = 0; mi < 2; mi++) {
                int r0 = warp_m * 32 + mi * 16 + g;
                a[mi][0] = f2tf32(As[r0 * LDA + kk]);
                a[mi][1] = f2tf32(As[(r0 + 8) * LDA + kk]);
                a[mi][2] = f2tf32(As[r0 * LDA + kk + 4]);
                a[mi][3] = f2tf32(As[(r0 + 8) * LDA + kk + 4]);
            }
            uint32_t b[8][2];
#pragma unroll
            for (int ni = 0; ni < 8; ni++) {
                int n = warp_n * 64 + ni * 8 + g;
                b[ni][0] = f2tf32(Bs[kk * LDB + n]);
                b[ni][1] = f2tf32(Bs[(kk + 4) * LDB + n]);
            }
#pragma unroll
            for (int mi = 0; mi < 2; mi++)
#pragma unroll
                for (int ni = 0; ni < 8; ni++)
                    mma_tf32(acc[mi][ni], a[mi], b[ni]);
        }
        __syncthreads();
    }

    // ---- epilogue: bias + rotary(Q,K only) + store ----
#pragma unroll
    for (int mi = 0; mi < 2; mi++) {
#pragma unroll
        for (int half = 0; half < 2; half++) {   // rows g / g+8
            int row = mb * BM + warp_m * 32 + mi * 16 + g + half * 8;  // token
            int pos = row & (SEQLEN - 1);
            float* orow = Og + (size_t)row * DMODEL;
            const float2* sct = g_sincos + pos * 32;
            int r0 = half * 2;   // acc regs {0,1} or {2,3}
#pragma unroll
            for (int ni = 0; ni < 8; ni++) {
                int e = warp_n * 64 + ni * 8 + c * 2;   // even column in head
                float v0 = acc[mi][ni][r0]     + bias[e];
                float v1 = acc[mi][ni][r0 + 1] + bias[e + 1];
                if (do_rot && e < ROT_DIM) {
                    float2 sc = sct[e >> 1];   // x=sin, y=cos
                    float o0 = v0 * sc.y - v1 * sc.x;
                    float o1 = v1 * sc.y + v0 * sc.x;
                    v0 = o0; v1 = o1;
                }
                float2 pr = make_float2(v0, v1);
                *reinterpret_cast<float2*>(orow + e) = pr;
            }
        }
    }
}

// ---------------------------------------------------------------------------
extern "C" void kernel_launch(void* const* d_in, const int* in_sizes, int n_in,
                              void* d_out, int out_size) {
    const float* residual = (const float*)d_in[0];
    const float* x        = (const float*)d_in[1];
    const float* WQ       = (const float*)d_in[2];
    const float* WK       = (const float*)d_in[3];
    const float* WV       = (const float*)d_in[4];
    const float* bQ       = (const float*)d_in[5];
    const float* bK       = (const float*)d_in[6];
    const float* bV       = (const float*)d_in[7];
    float* out = (float*)d_out;

    // residual passthrough: 16,777,216 floats = 4,194,304 float4
    copy_kernel<<<4096, 256>>>((float4*)out, (const float4*)residual,
                               (TOKENS * DMODEL) / 4);

    // rotary sin/cos table (2048 x 32)
    sincos_kernel<<<256, 256>>>();

    // fused QKV GEMM + bias + rotary
    cudaFuncSetAttribute(qkv_gemm_kernel,
                         cudaFuncAttributeMaxDynamicSharedMemorySize, SMEM_BYTES);
    dim3 grid(48, 64);
    qkv_gemm_kernel<<<grid, 256, SMEM_BYTES>>>(x, WQ, WK, WV, bQ, bK, bV, out);
}

// round 9
// speedup vs baseline: 1.1225x; 1.1225x over previous
#include <cuda_runtime.h>
#include <cuda_bf16.h>
#include <cstdint>

// ---------------------------------------------------------------------------
// AttentionIn via legacy mma.sync tf32 (sm_103 base target; no tcgen05 avail)
// out = concat(residual, q, k, v); q/k rotary on first 64 dims/head, v plain
// Pre-rounded operands (rna->tf32) eliminate all inner-loop CVTs.
// W pre-transposed to K-major so A and B share one conflict-free smem layout.
// ---------------------------------------------------------------------------

#define TOKENS   8192
#define DMODEL   2048
#define NTOT     6144            // 3 mats * 16 heads * 128
#define DHEAD    128
#define SEQLEN   2048
#define ROT_DIM  64

#define BM 128
#define BN 128
#define BK 32
#define LDT 36                   // smem row stride (floats) for A and B tiles
#define A_F (BM * LDT)           // 4608 floats
#define B_F (BN * LDT)           // 4608 floats
#define STAGE_F (A_F + B_F)      // 9216 floats
#define SMEM_BYTES (2 * STAGE_F * 4)   // 73728 bytes

// scratch (module-static device memory; no runtime allocation)
__device__ float  g_xr[TOKENS * DMODEL];        // rna(tf32)-rounded x
__device__ float  g_wt[(size_t)NTOT * DMODEL];  // W K-major [n][k], rounded
__device__ float2 g_sincos[SEQLEN * 32];        // [pos][pair] -> (sin, cos)

// ---------------------------------------------------------------------------
__device__ __forceinline__ uint32_t f2tf32(float f) {
    uint32_t r;
    asm("cvt.rna.tf32.f32 %0, %1;" : "=r"(r) : "f"(f));
    return r;
}
__device__ __forceinline__ void cp_async16(void* smem_ptr, const void* gmem_ptr) {
    unsigned s = (unsigned)__cvta_generic_to_shared(smem_ptr);
    asm volatile("cp.async.cg.shared.global [%0], [%1], 16;\n" :: "r"(s), "l"(gmem_ptr));
}
__device__ __forceinline__ void cp_commit() {
    asm volatile("cp.async.commit_group;\n");
}
template <int N>
__device__ __forceinline__ void cp_wait() {
    asm volatile("cp.async.wait_group %0;\n" :: "n"(N));
}
__device__ __forceinline__ void mma_tf32(float (&d)[4], const uint32_t (&a)[4],
                                         const uint32_t (&b)[2]) {
    asm volatile(
        "mma.sync.aligned.m16n8k8.row.col.f32.tf32.tf32.f32 "
        "{%0,%1,%2,%3}, {%4,%5,%6,%7}, {%8,%9}, {%0,%1,%2,%3};"
        : "+f"(d[0]), "+f"(d[1]), "+f"(d[2]), "+f"(d[3])
        : "r"(a[0]), "r"(a[1]), "r"(a[2]), "r"(a[3]), "r"(b[0]), "r"(b[1]));
}

// ---------------------------------------------------------------------------
// prep kernels
// ---------------------------------------------------------------------------
__global__ void sincos_kernel() {
    int idx = blockIdx.x * blockDim.x + threadIdx.x;   // 65536
    int pos = idx >> 5, i = idx & 31;
    float freq = powf(10000.0f, (float)i * (1.0f / 32.0f));
    float ang  = (float)pos / freq;
    g_sincos[idx] = make_float2(sinf(ang), cosf(ang));
}

__global__ void copy_kernel(float4* __restrict__ dst, const float4* __restrict__ src, int n) {
    int i = blockIdx.x * blockDim.x + threadIdx.x;
    int stride = gridDim.x * blockDim.x;
    for (; i < n; i += stride) dst[i] = src[i];
}

__global__ void roundx_kernel(const float4* __restrict__ x, int n) {
    float4* dst = reinterpret_cast<float4*>(g_xr);
    int i = blockIdx.x * blockDim.x + threadIdx.x;
    int stride = gridDim.x * blockDim.x;
    for (; i < n; i += stride) {
        float4 v = x[i];
        v.x = __uint_as_float(f2tf32(v.x));
        v.y = __uint_as_float(f2tf32(v.y));
        v.z = __uint_as_float(f2tf32(v.z));
        v.w = __uint_as_float(f2tf32(v.w));
        dst[i] = v;
    }
}

// W[mat][head][k][nin] -> g_wt[(mat*16+head)*128 + nin][k], rna-rounded
__global__ void wprep_kernel(const float* __restrict__ WQ,
                             const float* __restrict__ WK,
                             const float* __restrict__ WV) {
    __shared__ float t[32][33];
    int n0 = blockIdx.x * 32;     // 192 tiles over n
    int k0 = blockIdx.y * 32;     // 64 tiles over k
    int tx = threadIdx.x, ty = threadIdx.y;   // 32 x 8
#pragma unroll
    for (int j = 0; j < 4; j++) {
        int n = n0 + tx;
        int k = k0 + ty + j * 8;
        int mat = n >> 11;
        int rest = n & 2047;                 // head*128 + nin
        const float* W = (mat == 0) ? WQ : (mat == 1) ? WK : WV;
        float v = W[(size_t)(rest >> 7) * DMODEL * DHEAD + (size_t)k * DHEAD + (rest & 127)];
        t[ty + j * 8][tx] = __uint_as_float(f2tf32(v));
    }
    __syncthreads();
#pragma unroll
    for (int j = 0; j < 4; j++) {
        int n = n0 + ty + j * 8;
        int k = k0 + tx;
        g_wt[(size_t)n * DMODEL + k] = t[tx][ty + j * 8];
    }
}

// ---------------------------------------------------------------------------
// GEMM: gridDim = (48 [mat*16+head], 64 [M tiles]), 256 threads, 8 warps (4m x 2n)
// ---------------------------------------------------------------------------
__global__ void __launch_bounds__(256, 2)
qkv_gemm_kernel(const float* __restrict__ bQ, const float* __restrict__ bK,
                const float* __restrict__ bV, float* __restrict__ out) {
    extern __shared__ float smem[];

    const int nb   = blockIdx.x;           // 0..47
    const int mb   = blockIdx.y;           // 0..63
    const int mat  = nb >> 4;              // 0=Q, 1=K, 2=V
    const int head = nb & 15;

    const float* Ag = g_xr + (size_t)mb * BM * DMODEL;
    const float* Bg = g_wt + (size_t)nb * BN * DMODEL;    // K-major [128 n][2048 k]
    const float* bsel = (mat == 0) ? bQ : (mat == 1) ? bK : bV;
    const float* bias = bsel + head * DHEAD;
    float* Og = out + (size_t)(mat + 1) * TOKENS * DMODEL + head * DHEAD;

    const bool do_rot = (mat < 2);         // rotary on Q/K only

    const int tid    = threadIdx.x;
    const int wid    = tid >> 5;
    const int lane   = tid & 31;
    const int warp_m = wid >> 1;           // 0..3 -> m offset *32
    const int warp_n = wid & 1;            // 0..1 -> n offset *64
    const int g      = lane >> 2;          // groupID
    const int c      = lane & 3;           // threadID_in_group

    float acc[2][8][4];
#pragma unroll
    for (int mi = 0; mi < 2; mi++)
#pragma unroll
        for (int ni = 0; ni < 8; ni++)
#pragma unroll
            for (int r = 0; r < 4; r++) acc[mi][ni][r] = 0.0f;

    // ---- stage loader: both tiles are [128 rows][32 k], stride LDT=36 ----
    // cp.async dst granule: row*144B + s*16B (16B aligned since 144 = 9*16)
    auto load_stage = [&](int buf, int k0) {
        float* As = smem + buf * STAGE_F;
        float* Bs = As + A_F;
#pragma unroll
        for (int i = 0; i < 4; i++) {          // A: 1024 x 16B segs
            int id = tid + i * 256;
            int r = id >> 3, s = id & 7;
            cp_async16(As + r * LDT + s * 4, Ag + (size_t)r * DMODEL + k0 + s * 4);
        }
#pragma unroll
        for (int i = 0; i < 4; i++) {          // B: 1024 x 16B segs
            int id = tid + i * 256;
            int r = id >> 3, s = id & 7;
            cp_async16(Bs + r * LDT + s * 4, Bg + (size_t)r * DMODEL + k0 + s * 4);
        }
        cp_commit();
    };

    const int KT = DMODEL / BK;   // 64
    load_stage(0, 0);

    for (int kt = 0; kt < KT; kt++) {
        if (kt + 1 < KT) {
            load_stage((kt + 1) & 1, (kt + 1) * BK);
            cp_wait<1>();
        } else {
            cp_wait<0>();
        }
        __syncthreads();

        // operands are pre-rounded tf32 bit patterns: load as uint32, no cvt
        const uint32_t* As = reinterpret_cast<const uint32_t*>(smem + (kt & 1) * STAGE_F);
        const uint32_t* Bs = As + A_F;

#pragma unroll
        for (int ks = 0; ks < 4; ks++) {
            const int kk = ks * 8 + c;
            uint32_t a[2][4];
#pragma unroll
            for (int mi = 0; mi < 2; mi++) {
                int r0 = warp_m * 32 + mi * 16 + g;
                a[mi][0] = As[r0 * LDT + kk];
                a[mi][1] = As[(r0 + 8) * LDT + kk];
                a[mi][2] = As[r0 * LDT + kk + 4];
                a[mi][3] = As[(r0 + 8) * LDT + kk + 4];
            }
            uint32_t b[8][2];
#pragma unroll
            for (int ni = 0; ni < 8; ni++) {
                int n = warp_n * 64 + ni * 8 + g;       // B row (K-major)
                b[ni][0] = Bs[n * LDT + kk];
                b[ni][1] = Bs[n * LDT + kk + 4];
            }
#pragma unroll
            for (int mi = 0; mi < 2; mi++)
#pragma unroll
                for (int ni = 0; ni < 8; ni++)
                    mma_tf32(acc[mi][ni], a[mi], b[ni]);
        }
        __syncthreads();
    }

    // ---- epilogue: bias + rotary(Q,K only) + store ----
#pragma unroll
    for (int mi = 0; mi < 2; mi++) {
#pragma unroll
        for (int half = 0; half < 2; half++) {   // rows g / g+8
            int row = mb * BM + warp_m * 32 + mi * 16 + g + half * 8;  // token
            int pos = row & (SEQLEN - 1);
            float* orow = Og + (size_t)row * DMODEL;
            const float2* sct = g_sincos + pos * 32;
            int r0 = half * 2;   // acc regs {0,1} or {2,3}
#pragma unroll
            for (int ni = 0; ni < 8; ni++) {
                int e = warp_n * 64 + ni * 8 + c * 2;   // even column in head
                float v0 = acc[mi][ni][r0]     + bias[e];
                float v1 = acc[mi][ni][r0 + 1] + bias[e + 1];
                if (do_rot && e < ROT_DIM) {
                    float2 sc = sct[e >> 1];   // x=sin, y=cos
                    float o0 = v0 * sc.y - v1 * sc.x;
                    float o1 = v1 * sc.y + v0 * sc.x;
                    v0 = o0; v1 = o1;
                }
                *reinterpret_cast<float2*>(orow + e) = make_float2(v0, v1);
            }
        }
    }
}

// ---------------------------------------------------------------------------
extern "C" void kernel_launch(void* const* d_in, const int* in_sizes, int n_in,
                              void* d_out, int out_size) {
    const float* residual = (const float*)d_in[0];
    const float* x        = (const float*)d_in[1];
    const float* WQ       = (const float*)d_in[2];
    const float* WK       = (const float*)d_in[3];
    const float* WV       = (const float*)d_in[4];
    const float* bQ       = (const float*)d_in[5];
    const float* bK       = (const float*)d_in[6];
    const float* bV       = (const float*)d_in[7];
    float* out = (float*)d_out;

    // residual passthrough: 4,194,304 float4
    copy_kernel<<<4096, 256>>>((float4*)out, (const float4*)residual,
                               (TOKENS * DMODEL) / 4);
    // prep: rna-rounded x, transposed+rounded W (K-major), rotary table
    roundx_kernel<<<4096, 256>>>((const float4*)x, (TOKENS * DMODEL) / 4);
    wprep_kernel<<<dim3(NTOT / 32, DMODEL / 32), dim3(32, 8)>>>(WQ, WK, WV);
    sincos_kernel<<<256, 256>>>();

    // fused QKV GEMM + bias + rotary
    cudaFuncSetAttribute(qkv_gemm_kernel,
                         cudaFuncAttributeMaxDynamicSharedMemorySize, SMEM_BYTES);
    dim3 grid(48, 64);
    qkv_gemm_kernel<<<grid, 256, SMEM_BYTES>>>(bQ, bK, bV, out);
}